// round 13
// baseline (speedup 1.0000x reference)
#include <cuda_runtime.h>

#define B_SZ  2048
#define D_SZ  3072
#define H1_SZ 512
#define H2_SZ 256
#define F_SZ  100

// Scratch (no allocation allowed) — 7.6 MB total
__device__ float g_h1[B_SZ * H1_SZ];   // 4 MB
__device__ float g_h2[B_SZ * H2_SZ];   // 2 MB
__device__ float g_mt[F_SZ * B_SZ];    // m transposed [F][B], 0.8 MB
__device__ float g_ft[F_SZ * B_SZ];    // feats transposed [F][B], 0.8 MB

// ---------------------------------------------------------------------------
// Tiled fp32 GEMM:  C = act(A[M,K] @ W[K,N] + bias),  act = LeakyReLU(0.2)
// ---------------------------------------------------------------------------
template<int BM, int BN, int BK, int TM, int TN>
__global__ __launch_bounds__((BM/TM)*(BN/TN))
void gemm_bias_lrelu(const float* __restrict__ A, const float* __restrict__ W,
                     const float* __restrict__ bias, float* __restrict__ C,
                     int M, int N, int K, int do_act)
{
    constexpr int THREADS = (BM/TM)*(BN/TN);
    __shared__ float As[BK][BM];   // A tile, transposed for coalesced compute reads
    __shared__ float Ws[BK][BN];

    const int tid  = threadIdx.x;
    const int brow = blockIdx.y * BM;
    const int bcol = blockIdx.x * BN;
    const int tx = tid % (BN/TN);
    const int ty = tid / (BN/TN);

    // A-tile load mapping (float4 granularity)
    constexpr int ATPR  = BK / 4;            // threads per A row
    constexpr int ARPP  = THREADS / ATPR;    // rows per pass
    constexpr int APASS = BM / ARPP;
    const int a_row = tid / ATPR;
    const int a_col = (tid % ATPR) * 4;

    // W-tile load mapping
    constexpr int WTPR  = BN / 4;
    constexpr int WRPP  = THREADS / WTPR;
    constexpr int WPASS = BK / WRPP;
    const int w_row = tid / WTPR;
    const int w_col = (tid % WTPR) * 4;

    float acc[TM][TN];
#pragma unroll
    for (int i = 0; i < TM; i++)
#pragma unroll
        for (int j = 0; j < TN; j++) acc[i][j] = 0.f;

    for (int k0 = 0; k0 < K; k0 += BK) {
#pragma unroll
        for (int p = 0; p < APASS; p++) {
            int r = a_row + p * ARPP;
            float4 v = *reinterpret_cast<const float4*>(
                A + (size_t)(brow + r) * K + k0 + a_col);
            As[a_col + 0][r] = v.x;
            As[a_col + 1][r] = v.y;
            As[a_col + 2][r] = v.z;
            As[a_col + 3][r] = v.w;
        }
#pragma unroll
        for (int p = 0; p < WPASS; p++) {
            int r = w_row + p * WRPP;
            *reinterpret_cast<float4*>(&Ws[r][w_col]) =
                *reinterpret_cast<const float4*>(
                    W + (size_t)(k0 + r) * N + bcol + w_col);
        }
        __syncthreads();

#pragma unroll
        for (int kk = 0; kk < BK; kk++) {
            float af[TM], wf[TN];
#pragma unroll
            for (int i = 0; i < TM; i++) af[i] = As[kk][ty * TM + i];
#pragma unroll
            for (int j = 0; j < TN; j++) wf[j] = Ws[kk][tx * TN + j];
#pragma unroll
            for (int i = 0; i < TM; i++)
#pragma unroll
                for (int j = 0; j < TN; j++)
                    acc[i][j] = fmaf(af[i], wf[j], acc[i][j]);
        }
        __syncthreads();
    }

#pragma unroll
    for (int i = 0; i < TM; i++) {
        int row = brow + ty * TM + i;
#pragma unroll
        for (int j = 0; j < TN; j++) {
            int col = bcol + tx * TN + j;
            float v = acc[i][j] + bias[col];
            if (do_act) v = fmaxf(v, 0.2f * v);   // LeakyReLU(0.2)
            C[(size_t)row * N + col] = v;
        }
    }
}

// ---------------------------------------------------------------------------
// GEMM3: mT[f][i] = sum_k h2[i][k] * T[k][f]   (stores m TRANSPOSED)
// block = 128 threads (f = tid, f<100 active), handles 16 rows i.
// ---------------------------------------------------------------------------
__global__ __launch_bounds__(128)
void gemm3_mt_kernel(const float* __restrict__ h2, const float* __restrict__ T,
                     float* __restrict__ mt)
{
    __shared__ float sh[16][H2_SZ];          // 16 KB
    const int i0 = blockIdx.x * 16;
    for (int t = threadIdx.x; t < 16 * H2_SZ; t += 128)
        sh[t >> 8][t & (H2_SZ - 1)] = h2[(size_t)(i0 + (t >> 8)) * H2_SZ + (t & (H2_SZ - 1))];
    __syncthreads();

    const int f = threadIdx.x;
    if (f < F_SZ) {
        float acc[16];
#pragma unroll
        for (int r = 0; r < 16; r++) acc[r] = 0.f;
        for (int k = 0; k < H2_SZ; k++) {
            float tv = T[(size_t)k * F_SZ + f];   // coalesced across f
#pragma unroll
            for (int r = 0; r < 16; r++)
                acc[r] = fmaf(sh[r][k], tv, acc[r]);
        }
#pragma unroll
        for (int r = 0; r < 16; r++)
            mt[(size_t)f * B_SZ + i0 + r] = acc[r];
    }
}

// ---------------------------------------------------------------------------
// Minibatch discrimination: ftT[f][i] = sum_j exp(-|mT[f][i] - mT[f][j]|)
// grid = (B/256 i-tiles, F columns). Column cached in shared; col[j] broadcasts.
// MUFU(EX2)-bound.
// ---------------------------------------------------------------------------
__global__ __launch_bounds__(256)
void feats_kernel(const float* __restrict__ mt, float* __restrict__ ft)
{
    __shared__ float col[B_SZ];              // 8 KB
    const int f = blockIdx.y;
    const float* src = mt + (size_t)f * B_SZ;
    for (int t = threadIdx.x; t < B_SZ; t += 256)
        col[t] = src[t];
    __syncthreads();

    const int i = blockIdx.x * 256 + threadIdx.x;
    const float v = col[i];
    float s = 0.f;
#pragma unroll 8
    for (int j = 0; j < B_SZ; j++)
        s += __expf(-fabsf(v - col[j]));     // FADD + FMUL(|.|,-log2e) + MUFU.EX2 + FADD
    ft[(size_t)f * B_SZ + i] = s;
}

// ---------------------------------------------------------------------------
// Final: out[i] = h2[i,:] . Wf[0:256] + ftT[:,i] . Wf[256:356] + bf
// One block (128 threads) per row, deterministic shared reduction.
// ---------------------------------------------------------------------------
__global__ __launch_bounds__(128)
void final_kernel(const float* __restrict__ h2, const float* __restrict__ ft,
                  const float* __restrict__ Wf, const float* __restrict__ bf,
                  float* __restrict__ out)
{
    const int i = blockIdx.x;
    const int t = threadIdx.x;
    float acc = h2[(size_t)i * H2_SZ + t]       * Wf[t]
              + h2[(size_t)i * H2_SZ + t + 128] * Wf[t + 128];
    if (t < F_SZ)
        acc += ft[(size_t)t * B_SZ + i] * Wf[H2_SZ + t];

    __shared__ float red[128];
    red[t] = acc;
    __syncthreads();
#pragma unroll
    for (int s = 64; s > 0; s >>= 1) {
        if (t < s) red[t] += red[t + s];
        __syncthreads();
    }
    if (t == 0) out[i] = red[0] + bf[0];
}

// ---------------------------------------------------------------------------
extern "C" void kernel_launch(void* const* d_in, const int* in_sizes, int n_in,
                              void* d_out, int out_size)
{
    const float* x  = (const float*)d_in[0];   // (2048, 3072)
    const float* W1 = (const float*)d_in[1];   // (3072, 512)
    const float* b1 = (const float*)d_in[2];   // (512)
    const float* W2 = (const float*)d_in[3];   // (512, 256)
    const float* b2 = (const float*)d_in[4];   // (256)
    const float* T  = (const float*)d_in[5];   // (256, 100)
    const float* Wf = (const float*)d_in[6];   // (356, 1)
    const float* bf = (const float*)d_in[7];   // (1)
    float* out = (float*)d_out;                // (2048, 1)

    float *h1, *h2, *mt, *ft;
    cudaGetSymbolAddress((void**)&h1, g_h1);
    cudaGetSymbolAddress((void**)&h2, g_h2);
    cudaGetSymbolAddress((void**)&mt, g_mt);
    cudaGetSymbolAddress((void**)&ft, g_ft);

    // GEMM1: (2048x3072)@(3072x512) + LReLU -> 128 blocks of 128x64
    gemm_bias_lrelu<128, 64, 16, 8, 4>
        <<<dim3(H1_SZ / 64, B_SZ / 128), 256>>>(x, W1, b1, h1, B_SZ, H1_SZ, D_SZ, 1);

    // GEMM2: (2048x512)@(512x256) + LReLU -> 128 blocks of 64x64
    gemm_bias_lrelu<64, 64, 16, 4, 4>
        <<<dim3(H2_SZ / 64, B_SZ / 64), 256>>>(h1, W2, b2, h2, B_SZ, H2_SZ, H1_SZ, 1);

    // GEMM3: m = h2 @ T, stored transposed as mT[100][2048]
    gemm3_mt_kernel<<<B_SZ / 16, 128>>>(h2, T, mt);

    // Minibatch discrimination features (transposed)
    feats_kernel<<<dim3(B_SZ / 256, F_SZ), 256>>>(mt, ft);

    // Final projection
    final_kernel<<<B_SZ, 128>>>(h2, ft, Wf, bf, out);
}

// round 14
// speedup vs baseline: 1.0006x; 1.0006x over previous
#include <cuda_runtime.h>

#define B_SZ  2048
#define D_SZ  3072
#define H1_SZ 512
#define H2_SZ 256
#define F_SZ  100

// Scratch (no allocation allowed) — 7.6 MB total
__device__ float g_h1[B_SZ * H1_SZ];   // 4 MB
__device__ float g_h2[B_SZ * H2_SZ];   // 2 MB
__device__ float g_mt[F_SZ * B_SZ];    // m transposed [F][B], 0.8 MB
__device__ float g_ft[F_SZ * B_SZ];    // feats transposed [F][B], 0.8 MB

// ---------------------------------------------------------------------------
// Tiled fp32 GEMM:  C = act(A[M,K] @ W[K,N] + bias),  act = LeakyReLU(0.2)
// ---------------------------------------------------------------------------
template<int BM, int BN, int BK, int TM, int TN>
__global__ __launch_bounds__((BM/TM)*(BN/TN))
void gemm_bias_lrelu(const float* __restrict__ A, const float* __restrict__ W,
                     const float* __restrict__ bias, float* __restrict__ C,
                     int M, int N, int K, int do_act)
{
    constexpr int THREADS = (BM/TM)*(BN/TN);
    __shared__ float As[BK][BM];   // A tile, transposed for coalesced compute reads
    __shared__ float Ws[BK][BN];

    const int tid  = threadIdx.x;
    const int brow = blockIdx.y * BM;
    const int bcol = blockIdx.x * BN;
    const int tx = tid % (BN/TN);
    const int ty = tid / (BN/TN);

    // A-tile load mapping (float4 granularity)
    constexpr int ATPR  = BK / 4;            // threads per A row
    constexpr int ARPP  = THREADS / ATPR;    // rows per pass
    constexpr int APASS = BM / ARPP;
    const int a_row = tid / ATPR;
    const int a_col = (tid % ATPR) * 4;

    // W-tile load mapping
    constexpr int WTPR  = BN / 4;
    constexpr int WRPP  = THREADS / WTPR;
    constexpr int WPASS = BK / WRPP;
    const int w_row = tid / WTPR;
    const int w_col = (tid % WTPR) * 4;

    float acc[TM][TN];
#pragma unroll
    for (int i = 0; i < TM; i++)
#pragma unroll
        for (int j = 0; j < TN; j++) acc[i][j] = 0.f;

    for (int k0 = 0; k0 < K; k0 += BK) {
#pragma unroll
        for (int p = 0; p < APASS; p++) {
            int r = a_row + p * ARPP;
            float4 v = *reinterpret_cast<const float4*>(
                A + (size_t)(brow + r) * K + k0 + a_col);
            As[a_col + 0][r] = v.x;
            As[a_col + 1][r] = v.y;
            As[a_col + 2][r] = v.z;
            As[a_col + 3][r] = v.w;
        }
#pragma unroll
        for (int p = 0; p < WPASS; p++) {
            int r = w_row + p * WRPP;
            *reinterpret_cast<float4*>(&Ws[r][w_col]) =
                *reinterpret_cast<const float4*>(
                    W + (size_t)(k0 + r) * N + bcol + w_col);
        }
        __syncthreads();

#pragma unroll
        for (int kk = 0; kk < BK; kk++) {
            float af[TM], wf[TN];
#pragma unroll
            for (int i = 0; i < TM; i++) af[i] = As[kk][ty * TM + i];
#pragma unroll
            for (int j = 0; j < TN; j++) wf[j] = Ws[kk][tx * TN + j];
#pragma unroll
            for (int i = 0; i < TM; i++)
#pragma unroll
                for (int j = 0; j < TN; j++)
                    acc[i][j] = fmaf(af[i], wf[j], acc[i][j]);
        }
        __syncthreads();
    }

#pragma unroll
    for (int i = 0; i < TM; i++) {
        int row = brow + ty * TM + i;
#pragma unroll
        for (int j = 0; j < TN; j++) {
            int col = bcol + tx * TN + j;
            float v = acc[i][j] + bias[col];
            if (do_act) v = fmaxf(v, 0.2f * v);   // LeakyReLU(0.2)
            C[(size_t)row * N + col] = v;
        }
    }
}

// ---------------------------------------------------------------------------
// GEMM3: mT[f][i] = sum_k h2[i][k] * T[k][f]   (stores m TRANSPOSED)
// block = 128 threads (f = tid, f<100 active), handles 16 rows i.
// ---------------------------------------------------------------------------
__global__ __launch_bounds__(128)
void gemm3_mt_kernel(const float* __restrict__ h2, const float* __restrict__ T,
                     float* __restrict__ mt)
{
    __shared__ float sh[16][H2_SZ];          // 16 KB
    const int i0 = blockIdx.x * 16;
    for (int t = threadIdx.x; t < 16 * H2_SZ; t += 128)
        sh[t >> 8][t & (H2_SZ - 1)] = h2[(size_t)(i0 + (t >> 8)) * H2_SZ + (t & (H2_SZ - 1))];
    __syncthreads();

    const int f = threadIdx.x;
    if (f < F_SZ) {
        float acc[16];
#pragma unroll
        for (int r = 0; r < 16; r++) acc[r] = 0.f;
        for (int k = 0; k < H2_SZ; k++) {
            float tv = T[(size_t)k * F_SZ + f];   // coalesced across f
#pragma unroll
            for (int r = 0; r < 16; r++)
                acc[r] = fmaf(sh[r][k], tv, acc[r]);
        }
#pragma unroll
        for (int r = 0; r < 16; r++)
            mt[(size_t)f * B_SZ + i0 + r] = acc[r];
    }
}

// ---------------------------------------------------------------------------
// Minibatch discrimination: ftT[f][i] = sum_j exp(-|mT[f][i] - mT[f][j]|)
// grid = (B/256 i-tiles, F columns). Column cached in shared; col[j] broadcasts.
// MUFU(EX2)-bound.
// ---------------------------------------------------------------------------
__global__ __launch_bounds__(256)
void feats_kernel(const float* __restrict__ mt, float* __restrict__ ft)
{
    __shared__ float col[B_SZ];              // 8 KB
    const int f = blockIdx.y;
    const float* src = mt + (size_t)f * B_SZ;
    for (int t = threadIdx.x; t < B_SZ; t += 256)
        col[t] = src[t];
    __syncthreads();

    const int i = blockIdx.x * 256 + threadIdx.x;
    const float v = col[i];
    float s = 0.f;
#pragma unroll 8
    for (int j = 0; j < B_SZ; j++)
        s += __expf(-fabsf(v - col[j]));     // FADD + FMUL(|.|,-log2e) + MUFU.EX2 + FADD
    ft[(size_t)f * B_SZ + i] = s;
}

// ---------------------------------------------------------------------------
// Final: out[i] = h2[i,:] . Wf[0:256] + ftT[:,i] . Wf[256:356] + bf
// One block (128 threads) per row, deterministic shared reduction.
// ---------------------------------------------------------------------------
__global__ __launch_bounds__(128)
void final_kernel(const float* __restrict__ h2, const float* __restrict__ ft,
                  const float* __restrict__ Wf, const float* __restrict__ bf,
                  float* __restrict__ out)
{
    const int i = blockIdx.x;
    const int t = threadIdx.x;
    float acc = h2[(size_t)i * H2_SZ + t]       * Wf[t]
              + h2[(size_t)i * H2_SZ + t + 128] * Wf[t + 128];
    if (t < F_SZ)
        acc += ft[(size_t)t * B_SZ + i] * Wf[H2_SZ + t];

    __shared__ float red[128];
    red[t] = acc;
    __syncthreads();
#pragma unroll
    for (int s = 64; s > 0; s >>= 1) {
        if (t < s) red[t] += red[t + s];
        __syncthreads();
    }
    if (t == 0) out[i] = red[0] + bf[0];
}

// ---------------------------------------------------------------------------
extern "C" void kernel_launch(void* const* d_in, const int* in_sizes, int n_in,
                              void* d_out, int out_size)
{
    const float* x  = (const float*)d_in[0];   // (2048, 3072)
    const float* W1 = (const float*)d_in[1];   // (3072, 512)
    const float* b1 = (const float*)d_in[2];   // (512)
    const float* W2 = (const float*)d_in[3];   // (512, 256)
    const float* b2 = (const float*)d_in[4];   // (256)
    const float* T  = (const float*)d_in[5];   // (256, 100)
    const float* Wf = (const float*)d_in[6];   // (356, 1)
    const float* bf = (const float*)d_in[7];   // (1)
    float* out = (float*)d_out;                // (2048, 1)

    float *h1, *h2, *mt, *ft;
    cudaGetSymbolAddress((void**)&h1, g_h1);
    cudaGetSymbolAddress((void**)&h2, g_h2);
    cudaGetSymbolAddress((void**)&mt, g_mt);
    cudaGetSymbolAddress((void**)&ft, g_ft);

    // GEMM1: (2048x3072)@(3072x512) + LReLU -> 128 blocks of 128x64
    gemm_bias_lrelu<128, 64, 16, 8, 4>
        <<<dim3(H1_SZ / 64, B_SZ / 128), 256>>>(x, W1, b1, h1, B_SZ, H1_SZ, D_SZ, 1);

    // GEMM2: (2048x512)@(512x256) + LReLU -> 128 blocks of 64x64
    gemm_bias_lrelu<64, 64, 16, 4, 4>
        <<<dim3(H2_SZ / 64, B_SZ / 64), 256>>>(h1, W2, b2, h2, B_SZ, H2_SZ, H1_SZ, 1);

    // GEMM3: m = h2 @ T, stored transposed as mT[100][2048]
    gemm3_mt_kernel<<<B_SZ / 16, 128>>>(h2, T, mt);

    // Minibatch discrimination features (transposed)
    feats_kernel<<<dim3(B_SZ / 256, F_SZ), 256>>>(mt, ft);

    // Final projection
    final_kernel<<<B_SZ, 128>>>(h2, ft, Wf, bf, out);
}